// round 16
// baseline (speedup 1.0000x reference)
#include <cuda_runtime.h>
#include <cuda_bf16.h>
#include <cstdint>

#define B_    32
#define NTOK  3136
#define NH    12
#define D_    32

// ---------------- scratch (device globals; no allocation allowed) -------------
__device__ __align__(16) float g_Q[(size_t)B_ * NH * NTOK * D_];   // [b*12+h][n][d]
__device__ __align__(16) float g_K[(size_t)B_ * NH * NTOK * D_];
__device__ __align__(16) float g_V[(size_t)B_ * NH * NTOK * D_];

#define XELEMS ((size_t)B_ * NTOK * 384)
__device__ __align__(16) __nv_bfloat16 g_Xh[XELEMS];
__device__ __align__(16) __nv_bfloat16 g_Xl[XELEMS];
__device__ __align__(16) __nv_bfloat16 g_Zh[XELEMS];
__device__ __align__(16) __nv_bfloat16 g_Zl[XELEMS];
// transposed weights, [n][k]: rows 0..1151 = qkv output cols, 1152..1535 = proj cols
__device__ __align__(16) __nv_bfloat16 g_WTh[1536 * 384];
__device__ __align__(16) __nv_bfloat16 g_WTl[1536 * 384];

// ---------------- helpers -------------------------------------------------------
__device__ __forceinline__ uint32_t smem_u32(const void* p) {
    uint32_t a;
    asm("{ .reg .u64 t; cvta.to.shared.u64 t, %1; cvt.u32.u64 %0, t; }" : "=r"(a) : "l"(p));
    return a;
}
__device__ __forceinline__ void cp16(uint32_t dst, const void* src) {
    asm volatile("cp.async.cg.shared.global [%0], [%1], 16;" :: "r"(dst), "l"(src));
}
__device__ __forceinline__ void ldm_x4(uint32_t* r, uint32_t a) {
    asm volatile("ldmatrix.sync.aligned.m8n8.x4.shared.b16 {%0,%1,%2,%3}, [%4];"
                 : "=r"(r[0]), "=r"(r[1]), "=r"(r[2]), "=r"(r[3]) : "r"(a));
}
__device__ __forceinline__ void ldm_x2(uint32_t* r, uint32_t a) {
    asm volatile("ldmatrix.sync.aligned.m8n8.x2.shared.b16 {%0,%1}, [%2];"
                 : "=r"(r[0]), "=r"(r[1]) : "r"(a));
}
__device__ __forceinline__ void mma16816(float* d, const uint32_t* a, const uint32_t* b) {
    asm volatile(
        "mma.sync.aligned.m16n8k16.row.col.f32.bf16.bf16.f32 "
        "{%0,%1,%2,%3}, {%4,%5,%6,%7}, {%8,%9}, {%0,%1,%2,%3};"
        : "+f"(d[0]), "+f"(d[1]), "+f"(d[2]), "+f"(d[3])
        : "r"(a[0]), "r"(a[1]), "r"(a[2]), "r"(a[3]), "r"(b[0]), "r"(b[1]));
}

// ---------------- fused split(X) + weight transpose/split ------------------------
__global__ void split_fused(const float4* __restrict__ src,
                            const float* __restrict__ Wq,
                            const float* __restrict__ Wkv,
                            const float* __restrict__ Wproj)
{
    if (blockIdx.x < 4704) {
        uint4* hiP = (uint4*)g_Xh;
        uint4* loP = (uint4*)g_Xl;
        const int n8 = (int)(XELEMS / 8);
        const int stride = 4704 * 256;
        for (int i = blockIdx.x * 256 + threadIdx.x; i < n8; i += stride) {
            float4 f0 = src[2 * i];
            float4 f1 = src[2 * i + 1];
            uint32_t a0 = __float_as_uint(f0.x), a1 = __float_as_uint(f0.y);
            uint32_t a2 = __float_as_uint(f0.z), a3 = __float_as_uint(f0.w);
            uint32_t b0 = __float_as_uint(f1.x), b1 = __float_as_uint(f1.y);
            uint32_t b2 = __float_as_uint(f1.z), b3 = __float_as_uint(f1.w);
            uint4 h;
            h.x = __byte_perm(a0, a1, 0x7632);
            h.y = __byte_perm(a2, a3, 0x7632);
            h.z = __byte_perm(b0, b1, 0x7632);
            h.w = __byte_perm(b2, b3, 0x7632);
            float l0 = f0.x - __uint_as_float(a0 & 0xFFFF0000u);
            float l1 = f0.y - __uint_as_float(a1 & 0xFFFF0000u);
            float l2 = f0.z - __uint_as_float(a2 & 0xFFFF0000u);
            float l3 = f0.w - __uint_as_float(a3 & 0xFFFF0000u);
            float l4 = f1.x - __uint_as_float(b0 & 0xFFFF0000u);
            float l5 = f1.y - __uint_as_float(b1 & 0xFFFF0000u);
            float l6 = f1.z - __uint_as_float(b2 & 0xFFFF0000u);
            float l7 = f1.w - __uint_as_float(b3 & 0xFFFF0000u);
            uint4 l;
            asm("cvt.rn.bf16x2.f32 %0, %1, %2;" : "=r"(l.x) : "f"(l1), "f"(l0));
            asm("cvt.rn.bf16x2.f32 %0, %1, %2;" : "=r"(l.y) : "f"(l3), "f"(l2));
            asm("cvt.rn.bf16x2.f32 %0, %1, %2;" : "=r"(l.z) : "f"(l5), "f"(l4));
            asm("cvt.rn.bf16x2.f32 %0, %1, %2;" : "=r"(l.w) : "f"(l7), "f"(l6));
            hiP[i] = h;
            loP[i] = l;
        }
    } else {
        int idx = (blockIdx.x - 4704) * 256 + threadIdx.x;
        if (idx >= 1536 * 384) return;
        int nrow = idx / 384, k = idx % 384;
        float v;
        if (nrow < 384)       v = Wq[(size_t)k * 384 + nrow];
        else if (nrow < 1152) v = Wkv[(size_t)k * 768 + (nrow - 384)];
        else                  v = Wproj[(size_t)k * 384 + (nrow - 1152)];
        uint32_t bits = __float_as_uint(v);
        float hf = __uint_as_float(bits & 0xFFFF0000u);
        g_WTh[idx] = __ushort_as_bfloat16((unsigned short)(bits >> 16));
        g_WTl[idx] = __float2bfloat16(v - hf);
    }
}

// ---------------- HMMA GEMM: 128x96 tile, chunk K=32, 2-stage, 3 CTAs/SM --------
#define ABUF   8192                  // 128 rows x 64B
#define BBUF   6144                  // 96 rows x 64B
#define AB2    (2 * ABUF)
#define STAGEB (2 * ABUF + 2 * BBUF) // 28672
#define SMEM_GEMM (2 * STAGEB)       // 57344

__device__ __forceinline__ uint32_t swz(int row, int seg) {
    return (uint32_t)(row * 64 + ((seg ^ ((row >> 1) & 3)) << 4));
}

__global__ __launch_bounds__(256, 3)
void gemm_mma(const float* __restrict__ bias, float* __restrict__ out, int mode)
{
    extern __shared__ __align__(16) char smem[];
    const uint32_t sb = smem_u32(smem);
    const int tid = threadIdx.x, lane = tid & 31, wid = tid >> 5;
    const int warpM = wid & 1, warpN = wid >> 1;    // 2 x 4 warps, N=24 per warpN
    const int rowBase = blockIdx.y * 128, colBase = blockIdx.x * 96;

    const __nv_bfloat16* Ahg = (mode == 0 ? g_Xh : g_Zh) + (size_t)rowBase * 384;
    const __nv_bfloat16* Alg = (mode == 0 ? g_Xl : g_Zl) + (size_t)rowBase * 384;
    const int brow = (mode == 0 ? 0 : 1152) + colBase;
    const __nv_bfloat16* Bhg = g_WTh + (size_t)brow * 384;
    const __nv_bfloat16* Blg = g_WTl + (size_t)brow * 384;

    // A loader: rows lr, lr+64; seg lc
    const int lr = tid >> 2, lc = tid & 3;
    const uint32_t ad0 = swz(lr, lc);
    const uint32_t ad1 = swz(lr + 64, lc);
    // B loader: 384 segs per buffer; thread t -> seg t, plus seg t+256 if t<128
    const int b0r = tid >> 2;                 // rows 0..63 (seg = tid)
    const int b1r = (tid + 256) >> 2;         // rows 64..95 (tid<128)
    const uint32_t bd0 = swz(b0r, lc);
    const uint32_t bd1 = swz(b1r, lc);

    float acc[4][3][4];
#pragma unroll
    for (int i = 0; i < 4; i++)
#pragma unroll
        for (int j = 0; j < 3; j++)
#pragma unroll
            for (int q = 0; q < 4; q++) acc[i][j][q] = 0.f;

    auto load_chunk = [&](int c, int stg) {
        const uint32_t base = sb + stg * STAGEB;
        const size_t ga0 = (size_t)lr * 384 + c * 32 + lc * 8;
        const size_t ga1 = (size_t)(lr + 64) * 384 + c * 32 + lc * 8;
        cp16(base + ad0,        Ahg + ga0);
        cp16(base + ad1,        Ahg + ga1);
        cp16(base + ABUF + ad0, Alg + ga0);
        cp16(base + ABUF + ad1, Alg + ga1);
        const size_t gb0 = (size_t)b0r * 384 + c * 32 + lc * 8;
        cp16(base + AB2 + bd0,        Bhg + gb0);
        cp16(base + AB2 + BBUF + bd0, Blg + gb0);
        if (tid < 128) {
            const size_t gb1 = (size_t)b1r * 384 + c * 32 + lc * 8;
            cp16(base + AB2 + bd1,        Bhg + gb1);
            cp16(base + AB2 + BBUF + bd1, Blg + gb1);
        }
        asm volatile("cp.async.commit_group;" ::: "memory");
    };

    const int rA = lane & 15;
    const int sA_hi = (lane >> 4) & 1;
    const int rB = (lane & 7) + ((lane & 16) ? 8 : 0);   // x4: 16 rows (2 tiles)
    const int sB_hi = (lane >> 3) & 1;
    const int rB2 = lane & 7;                             // x2: 8 rows (tile 2)
    const int sB2_hi = (lane >> 3) & 1;                   // lanes 0..15 meaningful

    auto ldB = [&](uint32_t bufBase, int kk, uint32_t (*bx)[2]) {
        const int sB = (kk >> 3) + sB_hi;
        uint32_t rr[4];
        ldm_x4(rr, bufBase + swz(warpN * 24 + rB, sB));
        bx[0][0] = rr[0]; bx[0][1] = rr[1];
        bx[1][0] = rr[2]; bx[1][1] = rr[3];
        uint32_t r2[2];
        ldm_x2(r2, bufBase + swz(warpN * 24 + 16 + rB2, (kk >> 3) + sB2_hi));
        bx[2][0] = r2[0]; bx[2][1] = r2[1];
    };

    auto kk_group = [&](uint32_t base, int kk) {
        const int sA = (kk >> 3) + sA_hi;
        uint32_t ax[4][4], bx[3][2];
        // lh: A <- Al, B <- Bh
#pragma unroll
        for (int i = 0; i < 4; i++)
            ldm_x4(ax[i], base + ABUF + swz(warpM * 64 + i * 16 + rA, sA));
        ldB(base + AB2, kk, bx);
#pragma unroll
        for (int i = 0; i < 4; i++)
#pragma unroll
            for (int j = 0; j < 3; j++) mma16816(acc[i][j], ax[i], bx[j]);
        // hh: A <- Ah, Bh reused
#pragma unroll
        for (int i = 0; i < 4; i++)
            ldm_x4(ax[i], base + swz(warpM * 64 + i * 16 + rA, sA));
#pragma unroll
        for (int i = 0; i < 4; i++)
#pragma unroll
            for (int j = 0; j < 3; j++) mma16816(acc[i][j], ax[i], bx[j]);
        // hl: B <- Bl, Ah reused
        ldB(base + AB2 + BBUF, kk, bx);
#pragma unroll
        for (int i = 0; i < 4; i++)
#pragma unroll
            for (int j = 0; j < 3; j++) mma16816(acc[i][j], ax[i], bx[j]);
    };

    load_chunk(0, 0);

    for (int c = 0; c < 12; c++) {
        asm volatile("cp.async.wait_group 0;" ::: "memory");
        __syncthreads();
        const uint32_t base = sb + (c & 1) * STAGEB;
        kk_group(base, 0);
        if (c + 1 < 12) load_chunk(c + 1, (c + 1) & 1);
        kk_group(base, 16);
    }

    // epilogue
#pragma unroll
    for (int j = 0; j < 3; j++) {
        const int cg = colBase + warpN * 24 + j * 8 + 2 * (lane & 3);
#pragma unroll
        for (int i = 0; i < 4; i++) {
            const int m = rowBase + warpM * 64 + i * 16 + (lane >> 2);
            if (mode == 0) {
                int bb = m / NTOK, n = m % NTOK;
                float* dst;
                int d;
                if (cg < 384) {
                    dst = g_Q + (((size_t)bb * 12 + (cg >> 5)) * NTOK + n) * 32;
                    d = cg & 31;
                } else {
                    int j2 = cg - 384;
                    float* basep = (j2 >= 384) ? g_V : g_K;
                    dst = basep + (((size_t)bb * 12 + ((j2 >> 5) % 12)) * NTOK + n) * 32;
                    d = j2 & 31;
                }
                *(float2*)(dst + d)          = make_float2(acc[i][j][0], acc[i][j][1]);
                *(float2*)(dst + d + 8 * 32) = make_float2(acc[i][j][2], acc[i][j][3]);
            } else {
                float b0 = bias[cg], b1 = bias[cg + 1];
                *(float2*)(out + (size_t)m * 384 + cg) =
                    make_float2(acc[i][j][0] + b0, acc[i][j][1] + b1);
                *(float2*)(out + (size_t)(m + 8) * 384 + cg) =
                    make_float2(acc[i][j][2] + b0, acc[i][j][3] + b1);
            }
        }
    }
}

// ---------------- windowed attention with inline depthwise conv ------------------
__device__ __forceinline__ void attn_body(
    int scaleId, int bid,
    const float* __restrict__ c1w, const float* __restrict__ c1b,
    const float* __restrict__ c2w, const float* __restrict__ c2b)
{
    __shared__ __align__(16) float sQ[49 * 36];
    __shared__ __align__(16) float sK[64 * 36];
    __shared__ __align__(16) float sV[52 * 36];
    __shared__ __align__(16) float sP[49 * 52];

    int nside, headOff, ntile;
    if (scaleId == 0)      { nside = 8; headOff = 0; ntile = 1;  }
    else if (scaleId == 1) { nside = 4; headOff = 4; ntile = 4;  }
    else                   { nside = 2; headOff = 8; ntile = 16; }

    const int nwin = nside * nside;
    const int rg = bid % nwin;
    const int hl = (bid / nwin) & 3;
    const int b  = bid / (nwin * 4);
    const int hb = rg / nside, wb = rg % nside;

    const size_t imgOff = ((size_t)(b * 12 + headOff + hl)) * NTOK * 32;
    const float* Qp = g_Q + imgOff;
    const float* Kp = g_K + imgOff;
    const float* Vp = g_V + imgOff;

    if (scaleId == 0) {
        for (int idx = threadIdx.x; idx < 49 * 32; idx += 256) {
            int p = idx >> 5, k = idx & 31;
            int yy = hb * 7 + p / 7, xx = wb * 7 + p % 7;
            int off = (yy * 56 + xx) * 32 + k;
            sQ[p * 36 + k] = Qp[off];
            sK[p * 36 + k] = Kp[off];
            sV[p * 36 + k] = Vp[off];
        }
    } else if (scaleId == 1) {
        for (int idx = threadIdx.x; idx < 49 * 32; idx += 256) {
            int p = idx >> 5, k = idx & 31;
            int yo = hb * 7 + p / 7, xo = wb * 7 + p % 7;
            float aq = c1b[k], ak = aq, av = aq;
#pragma unroll
            for (int i = 0; i < 2; i++)
#pragma unroll
                for (int j = 0; j < 2; j++) {
                    int off = ((2 * yo + i) * 56 + 2 * xo + j) * 32 + k;
                    float w = c1w[(i * 2 + j) * 32 + k];
                    aq = fmaf(Qp[off], w, aq);
                    ak = fmaf(Kp[off], w, ak);
                    av = fmaf(Vp[off], w, av);
                }
            sQ[p * 36 + k] = aq;
            sK[p * 36 + k] = ak;
            sV[p * 36 + k] = av;
        }
    } else {
        for (int idx = threadIdx.x; idx < 49 * 32; idx += 256) {
            int p = idx >> 5, k = idx & 31;
            int yo = hb * 7 + p / 7, xo = wb * 7 + p % 7;
            float aq = c2b[k], ak = aq, av = aq;
#pragma unroll
            for (int i = 0; i < 2; i++) {
                int iy = 4 * yo - 1 + 2 * i;
                if (iy < 0 || iy >= 56) continue;
#pragma unroll
                for (int j = 0; j < 2; j++) {
                    int ix = 4 * xo - 1 + 2 * j;
                    if (ix < 0 || ix >= 56) continue;
                    int off = (iy * 56 + ix) * 32 + k;
                    float w = c2w[(i * 2 + j) * 32 + k];
                    aq = fmaf(Qp[off], w, aq);
                    ak = fmaf(Kp[off], w, ak);
                    av = fmaf(Vp[off], w, av);
                }
            }
            sQ[p * 36 + k] = aq;
            sK[p * 36 + k] = ak;
            sV[p * 36 + k] = av;
        }
    }
    for (int idx = threadIdx.x; idx < 15 * 36; idx += 256) sK[49 * 36 + idx] = 0.f;
    for (int idx = threadIdx.x; idx < 3 * 36; idx += 256)  sV[49 * 36 + idx] = 0.f;
    for (int idx = threadIdx.x; idx < 49 * 3; idx += 256)
        sP[(idx / 3) * 52 + 49 + (idx % 3)] = 0.f;
    __syncthreads();

    const int lane = threadIdx.x & 31;
    const int warp = threadIdx.x >> 5;
    const float scale = 0.17677669529663687f;
    const bool hi = (lane < 17);

    float s0v[7], s1v[7];
#pragma unroll
    for (int i = 0; i < 7; i++) { s0v[i] = 0.f; s1v[i] = 0.f; }
#pragma unroll
    for (int half = 0; half < 2; half++) {
        float4 kA[4], kB[4];
#pragma unroll
        for (int j = 0; j < 4; j++) {
            kA[j] = *(const float4*)&sK[lane * 36 + 16 * half + 4 * j];
            kB[j] = *(const float4*)&sK[(lane + 32) * 36 + 16 * half + 4 * j];
        }
#pragma unroll
        for (int i = 0; i < 7; i++) {
            int p = warp + 8 * i;
            if (p < 49) {
                float s0 = 0.f, s1 = 0.f;
#pragma unroll
                for (int j = 0; j < 4; j++) {
                    float4 qv = *(const float4*)&sQ[p * 36 + 16 * half + 4 * j];
                    s0 = fmaf(qv.x, kA[j].x, s0); s0 = fmaf(qv.y, kA[j].y, s0);
                    s0 = fmaf(qv.z, kA[j].z, s0); s0 = fmaf(qv.w, kA[j].w, s0);
                    s1 = fmaf(qv.x, kB[j].x, s1); s1 = fmaf(qv.y, kB[j].y, s1);
                    s1 = fmaf(qv.z, kB[j].z, s1); s1 = fmaf(qv.w, kB[j].w, s1);
                }
                s0v[i] += s0;
                s1v[i] += s1;
            }
        }
    }
#pragma unroll
    for (int i = 0; i < 7; i++) { s0v[i] *= scale; s1v[i] *= scale; }

    float mx[7];
#pragma unroll
    for (int i = 0; i < 7; i++) mx[i] = hi ? fmaxf(s0v[i], s1v[i]) : s0v[i];
#pragma unroll
    for (int o = 16; o > 0; o >>= 1) {
#pragma unroll
        for (int i = 0; i < 7; i++)
            mx[i] = fmaxf(mx[i], __shfl_xor_sync(0xffffffffu, mx[i], o));
    }
    float e0a[7], e1a[7], sm[7];
#pragma unroll
    for (int i = 0; i < 7; i++) {
        e0a[i] = __expf(s0v[i] - mx[i]);
        e1a[i] = hi ? __expf(s1v[i] - mx[i]) : 0.f;
        sm[i] = e0a[i] + e1a[i];
    }
#pragma unroll
    for (int o = 16; o > 0; o >>= 1) {
#pragma unroll
        for (int i = 0; i < 7; i++)
            sm[i] += __shfl_xor_sync(0xffffffffu, sm[i], o);
    }
    float rinv[7];
#pragma unroll
    for (int i = 0; i < 7; i++) {
        rinv[i] = 1.f / sm[i];
        int p = warp + 8 * i;
        if (p < 49) {
            sP[p * 52 + lane] = e0a[i];
            if (lane < 17) sP[p * 52 + 32 + lane] = e1a[i];
        }
    }
    __syncthreads();

    float accv[7];
#pragma unroll
    for (int i = 0; i < 7; i++) accv[i] = 0.f;
#pragma unroll
    for (int j = 0; j < 13; j++) {
        float4 pv[7];
#pragma unroll
        for (int i = 0; i < 7; i++) {
            int p = warp + 8 * i;
            pv[i] = (p < 49) ? *(const float4*)&sP[p * 52 + 4 * j]
                             : make_float4(0.f, 0.f, 0.f, 0.f);
        }
        {
            float v0 = sV[(4 * j + 0) * 36 + lane];
#pragma unroll
            for (int i = 0; i < 7; i++) accv[i] = fmaf(pv[i].x, v0, accv[i]);
            float v1 = sV[(4 * j + 1) * 36 + lane];
#pragma unroll
            for (int i = 0; i < 7; i++) accv[i] = fmaf(pv[i].y, v1, accv[i]);
            float v2 = sV[(4 * j + 2) * 36 + lane];
#pragma unroll
            for (int i = 0; i < 7; i++) accv[i] = fmaf(pv[i].z, v2, accv[i]);
            float v3 = sV[(4 * j + 3) * 36 + lane];
#pragma unroll
            for (int i = 0; i < 7; i++) accv[i] = fmaf(pv[i].w, v3, accv[i]);
        }
    }

#pragma unroll
    for (int i = 0; i < 7; i++) {
        int p = warp + 8 * i;
        if (p < 49) {
            float val = accv[i] * rinv[i];
            __nv_bfloat16 h = __float2bfloat16(val);
            __nv_bfloat16 l = __float2bfloat16(val - __bfloat162float(h));
            int col = (headOff + hl) * 32 + lane;
            for (int t = 0; t < ntile; t++) {
                int nout = (t * nwin + rg) * 49 + p;
                size_t off = ((size_t)b * NTOK + nout) * 384 + col;
                g_Zh[off] = h;
                g_Zl[off] = l;
            }
        }
    }
}

// single launch, heavy (conv-bearing) CTAs scheduled first
__global__ __launch_bounds__(256, 3)
void attn_all(const float* __restrict__ c1w, const float* __restrict__ c1b,
              const float* __restrict__ c2w, const float* __restrict__ c2b)
{
    int bid = blockIdx.x;
    if (bid < 512)        attn_body(2, bid, c1w, c1b, c2w, c2b);
    else if (bid < 2560)  attn_body(1, bid - 512, c1w, c1b, c2w, c2b);
    else                  attn_body(0, bid - 2560, c1w, c1b, c2w, c2b);
}

// ---------------- launch ---------------------------------------------------------
extern "C" void kernel_launch(void* const* d_in, const int* in_sizes, int n_in,
                              void* d_out, int out_size)
{
    const float* x     = (const float*)d_in[0];
    const float* Wq    = (const float*)d_in[1];
    const float* Wkv   = (const float*)d_in[2];
    const float* Wproj = (const float*)d_in[3];
    const float* bproj = (const float*)d_in[4];
    const float* c1w   = (const float*)d_in[5];
    const float* c1b   = (const float*)d_in[6];
    const float* c2w   = (const float*)d_in[7];
    const float* c2b   = (const float*)d_in[8];
    float* out = (float*)d_out;

    cudaFuncSetAttribute(gemm_mma, cudaFuncAttributeMaxDynamicSharedMemorySize, SMEM_GEMM);

    split_fused<<<4704 + 2304, 256>>>((const float4*)x, Wq, Wkv, Wproj);
    gemm_mma<<<dim3(12, 784), 256, SMEM_GEMM>>>(nullptr, nullptr, 0);
    attn_all<<<10752, 256>>>(c1w, c1b, c2w, c2b);
    gemm_mma<<<dim3(4, 784), 256, SMEM_GEMM>>>(bproj, out, 1);      // 4th -> ncu
}

// round 17
// speedup vs baseline: 1.1083x; 1.1083x over previous
#include <cuda_runtime.h>
#include <cuda_bf16.h>
#include <cstdint>

#define B_    32
#define NTOK  3136
#define NH    12
#define D_    32

// ---------------- scratch (device globals; no allocation allowed) -------------
__device__ __align__(16) float g_Q[(size_t)B_ * NH * NTOK * D_];   // [b*12+h][n][d]
__device__ __align__(16) float g_K[(size_t)B_ * NH * NTOK * D_];
__device__ __align__(16) float g_V[(size_t)B_ * NH * NTOK * D_];

#define XELEMS ((size_t)B_ * NTOK * 384)
__device__ __align__(16) __nv_bfloat16 g_Xh[XELEMS];
__device__ __align__(16) __nv_bfloat16 g_Xl[XELEMS];
__device__ __align__(16) __nv_bfloat16 g_Zh[XELEMS];
__device__ __align__(16) __nv_bfloat16 g_Zl[XELEMS];
// transposed weights, [n][k]: rows 0..1151 = qkv output cols, 1152..1535 = proj cols
__device__ __align__(16) __nv_bfloat16 g_WTh[1536 * 384];
__device__ __align__(16) __nv_bfloat16 g_WTl[1536 * 384];

// ---------------- helpers -------------------------------------------------------
__device__ __forceinline__ uint32_t smem_u32(const void* p) {
    uint32_t a;
    asm("{ .reg .u64 t; cvta.to.shared.u64 t, %1; cvt.u32.u64 %0, t; }" : "=r"(a) : "l"(p));
    return a;
}
__device__ __forceinline__ void cp16(uint32_t dst, const void* src) {
    asm volatile("cp.async.cg.shared.global [%0], [%1], 16;" :: "r"(dst), "l"(src));
}
__device__ __forceinline__ void ldm_x4(uint32_t* r, uint32_t a) {
    asm volatile("ldmatrix.sync.aligned.m8n8.x4.shared.b16 {%0,%1,%2,%3}, [%4];"
                 : "=r"(r[0]), "=r"(r[1]), "=r"(r[2]), "=r"(r[3]) : "r"(a));
}
__device__ __forceinline__ void mma16816(float* d, const uint32_t* a, const uint32_t* b) {
    asm volatile(
        "mma.sync.aligned.m16n8k16.row.col.f32.bf16.bf16.f32 "
        "{%0,%1,%2,%3}, {%4,%5,%6,%7}, {%8,%9}, {%0,%1,%2,%3};"
        : "+f"(d[0]), "+f"(d[1]), "+f"(d[2]), "+f"(d[3])
        : "r"(a[0]), "r"(a[1]), "r"(a[2]), "r"(a[3]), "r"(b[0]), "r"(b[1]));
}

// ---------------- fused split(X) + weight transpose/split ------------------------
__global__ void split_fused(const float4* __restrict__ src,
                            const float* __restrict__ Wq,
                            const float* __restrict__ Wkv,
                            const float* __restrict__ Wproj)
{
    if (blockIdx.x < 4704) {
        uint4* hiP = (uint4*)g_Xh;
        uint4* loP = (uint4*)g_Xl;
        const int n8 = (int)(XELEMS / 8);
        const int stride = 4704 * 256;
        for (int i = blockIdx.x * 256 + threadIdx.x; i < n8; i += stride) {
            float4 f0 = src[2 * i];
            float4 f1 = src[2 * i + 1];
            uint32_t a0 = __float_as_uint(f0.x), a1 = __float_as_uint(f0.y);
            uint32_t a2 = __float_as_uint(f0.z), a3 = __float_as_uint(f0.w);
            uint32_t b0 = __float_as_uint(f1.x), b1 = __float_as_uint(f1.y);
            uint32_t b2 = __float_as_uint(f1.z), b3 = __float_as_uint(f1.w);
            uint4 h;
            h.x = __byte_perm(a0, a1, 0x7632);
            h.y = __byte_perm(a2, a3, 0x7632);
            h.z = __byte_perm(b0, b1, 0x7632);
            h.w = __byte_perm(b2, b3, 0x7632);
            float l0 = f0.x - __uint_as_float(a0 & 0xFFFF0000u);
            float l1 = f0.y - __uint_as_float(a1 & 0xFFFF0000u);
            float l2 = f0.z - __uint_as_float(a2 & 0xFFFF0000u);
            float l3 = f0.w - __uint_as_float(a3 & 0xFFFF0000u);
            float l4 = f1.x - __uint_as_float(b0 & 0xFFFF0000u);
            float l5 = f1.y - __uint_as_float(b1 & 0xFFFF0000u);
            float l6 = f1.z - __uint_as_float(b2 & 0xFFFF0000u);
            float l7 = f1.w - __uint_as_float(b3 & 0xFFFF0000u);
            uint4 l;
            asm("cvt.rn.bf16x2.f32 %0, %1, %2;" : "=r"(l.x) : "f"(l1), "f"(l0));
            asm("cvt.rn.bf16x2.f32 %0, %1, %2;" : "=r"(l.y) : "f"(l3), "f"(l2));
            asm("cvt.rn.bf16x2.f32 %0, %1, %2;" : "=r"(l.z) : "f"(l5), "f"(l4));
            asm("cvt.rn.bf16x2.f32 %0, %1, %2;" : "=r"(l.w) : "f"(l7), "f"(l6));
            hiP[i] = h;
            loP[i] = l;
        }
    } else {
        int idx = (blockIdx.x - 4704) * 256 + threadIdx.x;
        if (idx >= 1536 * 384) return;
        int nrow = idx / 384, k = idx % 384;
        float v;
        if (nrow < 384)       v = Wq[(size_t)k * 384 + nrow];
        else if (nrow < 1152) v = Wkv[(size_t)k * 768 + (nrow - 384)];
        else                  v = Wproj[(size_t)k * 384 + (nrow - 1152)];
        uint32_t bits = __float_as_uint(v);
        float hf = __uint_as_float(bits & 0xFFFF0000u);
        g_WTh[idx] = __ushort_as_bfloat16((unsigned short)(bits >> 16));
        g_WTl[idx] = __float2bfloat16(v - hf);
    }
}

// ---------------- HMMA GEMM: 128x128 tile, chunk K=32, 3-stage ring, swizzled ---
#define BUFB   (128 * 64)
#define STAGEB (4 * BUFB)
#define SMEM_GEMM (3 * STAGEB)

__device__ __forceinline__ uint32_t swz(int row, int seg) {
    return (uint32_t)(row * 64 + ((seg ^ ((row >> 1) & 3)) << 4));
}

__global__ __launch_bounds__(256, 2)
void gemm_mma(const float* __restrict__ bias, float* __restrict__ out, int mode)
{
    extern __shared__ __align__(16) char smem[];
    const uint32_t sb = smem_u32(smem);
    const int tid = threadIdx.x, lane = tid & 31, wid = tid >> 5;
    const int warpM = wid & 1, warpN = wid >> 1;
    const int rowBase = blockIdx.y * 128, colBase = blockIdx.x * 128;

    const __nv_bfloat16* Ahg = (mode == 0 ? g_Xh : g_Zh) + (size_t)rowBase * 384;
    const __nv_bfloat16* Alg = (mode == 0 ? g_Xl : g_Zl) + (size_t)rowBase * 384;
    const int brow = (mode == 0 ? 0 : 1152) + colBase;
    const __nv_bfloat16* Bhg = g_WTh + (size_t)brow * 384;
    const __nv_bfloat16* Blg = g_WTl + (size_t)brow * 384;

    const int lr = tid >> 2, lc = tid & 3;
    const uint32_t d0 = swz(lr, lc);
    const uint32_t d1 = swz(lr + 64, lc);

    float acc[4][4][4];
#pragma unroll
    for (int i = 0; i < 4; i++)
#pragma unroll
        for (int j = 0; j < 4; j++)
#pragma unroll
            for (int q = 0; q < 4; q++) acc[i][j][q] = 0.f;

    auto load_chunk = [&](int c, int stg) {
        const uint32_t base = sb + stg * STAGEB;
        const size_t g0 = (size_t)lr * 384 + c * 32 + lc * 8;
        const size_t g1 = (size_t)(lr + 64) * 384 + c * 32 + lc * 8;
        cp16(base + d0,             Ahg + g0);
        cp16(base + d1,             Ahg + g1);
        cp16(base + BUFB + d0,      Alg + g0);
        cp16(base + BUFB + d1,      Alg + g1);
        cp16(base + 2 * BUFB + d0,  Bhg + g0);
        cp16(base + 2 * BUFB + d1,  Bhg + g1);
        cp16(base + 3 * BUFB + d0,  Blg + g0);
        cp16(base + 3 * BUFB + d1,  Blg + g1);
        asm volatile("cp.async.commit_group;" ::: "memory");
    };

    const int rA = lane & 15;
    const int sA_hi = (lane >> 4) & 1;
    const int rB = (lane & 7) + ((lane & 16) ? 8 : 0);
    const int sB_hi = (lane >> 3) & 1;

    // per-kk-group body: lh -> hh -> hl, each operand LDSM'd exactly once
    auto kk_group = [&](uint32_t base, int kk) {
        const int sA = (kk >> 3) + sA_hi;
        const int sB = (kk >> 3) + sB_hi;
        uint32_t ax[4][4], bx[4][2];
#pragma unroll
        for (int i = 0; i < 4; i++)
            ldm_x4(ax[i], base + BUFB + swz(warpM * 64 + i * 16 + rA, sA));
#pragma unroll
        for (int jj = 0; jj < 2; jj++) {
            uint32_t rr[4];
            ldm_x4(rr, base + 2 * BUFB + swz(warpN * 32 + jj * 16 + rB, sB));
            bx[2 * jj][0] = rr[0]; bx[2 * jj][1] = rr[1];
            bx[2 * jj + 1][0] = rr[2]; bx[2 * jj + 1][1] = rr[3];
        }
#pragma unroll
        for (int i = 0; i < 4; i++)
#pragma unroll
            for (int j = 0; j < 4; j++) mma16816(acc[i][j], ax[i], bx[j]);
#pragma unroll
        for (int i = 0; i < 4; i++)
            ldm_x4(ax[i], base + swz(warpM * 64 + i * 16 + rA, sA));
#pragma unroll
        for (int i = 0; i < 4; i++)
#pragma unroll
            for (int j = 0; j < 4; j++) mma16816(acc[i][j], ax[i], bx[j]);
#pragma unroll
        for (int jj = 0; jj < 2; jj++) {
            uint32_t rr[4];
            ldm_x4(rr, base + 3 * BUFB + swz(warpN * 32 + jj * 16 + rB, sB));
            bx[2 * jj][0] = rr[0]; bx[2 * jj][1] = rr[1];
            bx[2 * jj + 1][0] = rr[2]; bx[2 * jj + 1][1] = rr[3];
        }
#pragma unroll
        for (int i = 0; i < 4; i++)
#pragma unroll
            for (int j = 0; j < 4; j++) mma16816(acc[i][j], ax[i], bx[j]);
    };

    load_chunk(0, 0);
    load_chunk(1, 1);

    for (int c = 0; c < 12; c++) {
        if (c < 11) asm volatile("cp.async.wait_group 1;" ::: "memory");
        else        asm volatile("cp.async.wait_group 0;" ::: "memory");
        __syncthreads();
        const uint32_t base = sb + (c % 3) * STAGEB;
        // start computing immediately; issue next chunk's loads under MMA cover
        kk_group(base, 0);
        if (c + 2 < 12) load_chunk(c + 2, (c + 2) % 3);
        kk_group(base, 16);
    }

    // epilogue
#pragma unroll
    for (int j = 0; j < 4; j++) {
        const int cg = colBase + warpN * 32 + j * 8 + 2 * (lane & 3);
#pragma unroll
        for (int i = 0; i < 4; i++) {
            const int m = rowBase + warpM * 64 + i * 16 + (lane >> 2);
            if (mode == 0) {
                int bb = m / NTOK, n = m % NTOK;
                float* dst;
                int d;
                if (cg < 384) {
                    dst = g_Q + (((size_t)bb * 12 + (cg >> 5)) * NTOK + n) * 32;
                    d = cg & 31;
                } else {
                    int j2 = cg - 384;
                    float* basep = (j2 >= 384) ? g_V : g_K;
                    dst = basep + (((size_t)bb * 12 + ((j2 >> 5) % 12)) * NTOK + n) * 32;
                    d = j2 & 31;
                }
                *(float2*)(dst + d)          = make_float2(acc[i][j][0], acc[i][j][1]);
                *(float2*)(dst + d + 8 * 32) = make_float2(acc[i][j][2], acc[i][j][3]);
            } else {
                float b0 = bias[cg], b1 = bias[cg + 1];
                *(float2*)(out + (size_t)m * 384 + cg) =
                    make_float2(acc[i][j][0] + b0, acc[i][j][1] + b1);
                *(float2*)(out + (size_t)(m + 8) * 384 + cg) =
                    make_float2(acc[i][j][2] + b0, acc[i][j][3] + b1);
            }
        }
    }
}

// ---------------- windowed attention with inline depthwise conv ------------------
__device__ __forceinline__ void attn_body(
    int scaleId, int bid,
    const float* __restrict__ c1w, const float* __restrict__ c1b,
    const float* __restrict__ c2w, const float* __restrict__ c2b)
{
    __shared__ __align__(16) float sQ[49 * 36];
    __shared__ __align__(16) float sK[64 * 36];
    __shared__ __align__(16) float sV[52 * 36];   // rows 49..51 zeroed
    __shared__ __align__(16) float sP[49 * 52];   // cols 49..51 zeroed

    int nside, headOff, ntile;
    if (scaleId == 0)      { nside = 8; headOff = 0; ntile = 1;  }
    else if (scaleId == 1) { nside = 4; headOff = 4; ntile = 4;  }
    else                   { nside = 2; headOff = 8; ntile = 16; }

    const int nwin = nside * nside;
    const int rg = bid % nwin;
    const int hl = (bid / nwin) & 3;
    const int b  = bid / (nwin * 4);
    const int hb = rg / nside, wb = rg % nside;

    const size_t imgOff = ((size_t)(b * 12 + headOff + hl)) * NTOK * 32;
    const float* Qp = g_Q + imgOff;
    const float* Kp = g_K + imgOff;
    const float* Vp = g_V + imgOff;

    if (scaleId == 0) {
        for (int idx = threadIdx.x; idx < 49 * 32; idx += 256) {
            int p = idx >> 5, k = idx & 31;
            int yy = hb * 7 + p / 7, xx = wb * 7 + p % 7;
            int off = (yy * 56 + xx) * 32 + k;
            sQ[p * 36 + k] = Qp[off];
            sK[p * 36 + k] = Kp[off];
            sV[p * 36 + k] = Vp[off];
        }
    } else if (scaleId == 1) {
        for (int idx = threadIdx.x; idx < 49 * 32; idx += 256) {
            int p = idx >> 5, k = idx & 31;
            int yo = hb * 7 + p / 7, xo = wb * 7 + p % 7;
            float aq = c1b[k], ak = aq, av = aq;
#pragma unroll
            for (int i = 0; i < 2; i++)
#pragma unroll
                for (int j = 0; j < 2; j++) {
                    int off = ((2 * yo + i) * 56 + 2 * xo + j) * 32 + k;
                    float w = c1w[(i * 2 + j) * 32 + k];
                    aq = fmaf(Qp[off], w, aq);
                    ak = fmaf(Kp[off], w, ak);
                    av = fmaf(Vp[off], w, av);
                }
            sQ[p * 36 + k] = aq;
            sK[p * 36 + k] = ak;
            sV[p * 36 + k] = av;
        }
    } else {
        for (int idx = threadIdx.x; idx < 49 * 32; idx += 256) {
            int p = idx >> 5, k = idx & 31;
            int yo = hb * 7 + p / 7, xo = wb * 7 + p % 7;
            float aq = c2b[k], ak = aq, av = aq;
#pragma unroll
            for (int i = 0; i < 2; i++) {
                int iy = 4 * yo - 1 + 2 * i;
                if (iy < 0 || iy >= 56) continue;
#pragma unroll
                for (int j = 0; j < 2; j++) {
                    int ix = 4 * xo - 1 + 2 * j;
                    if (ix < 0 || ix >= 56) continue;
                    int off = (iy * 56 + ix) * 32 + k;
                    float w = c2w[(i * 2 + j) * 32 + k];
                    aq = fmaf(Qp[off], w, aq);
                    ak = fmaf(Kp[off], w, ak);
                    av = fmaf(Vp[off], w, av);
                }
            }
            sQ[p * 36 + k] = aq;
            sK[p * 36 + k] = ak;
            sV[p * 36 + k] = av;
        }
    }
    for (int idx = threadIdx.x; idx < 15 * 36; idx += 256) sK[49 * 36 + idx] = 0.f;
    for (int idx = threadIdx.x; idx < 3 * 36; idx += 256)  sV[49 * 36 + idx] = 0.f;
    for (int idx = threadIdx.x; idx < 49 * 3; idx += 256)
        sP[(idx / 3) * 52 + 49 + (idx % 3)] = 0.f;
    __syncthreads();

    const int lane = threadIdx.x & 31;
    const int warp = threadIdx.x >> 5;
    const float scale = 0.17677669529663687f;
    const bool hi = (lane < 17);

    float s0v[7], s1v[7];
#pragma unroll
    for (int i = 0; i < 7; i++) { s0v[i] = 0.f; s1v[i] = 0.f; }
#pragma unroll
    for (int half = 0; half < 2; half++) {
        float4 kA[4], kB[4];
#pragma unroll
        for (int j = 0; j < 4; j++) {
            kA[j] = *(const float4*)&sK[lane * 36 + 16 * half + 4 * j];
            kB[j] = *(const float4*)&sK[(lane + 32) * 36 + 16 * half + 4 * j];
        }
#pragma unroll
        for (int i = 0; i < 7; i++) {
            int p = warp + 8 * i;
            if (p < 49) {
                float s0 = 0.f, s1 = 0.f;
#pragma unroll
                for (int j = 0; j < 4; j++) {
                    float4 qv = *(const float4*)&sQ[p * 36 + 16 * half + 4 * j];
                    s0 = fmaf(qv.x, kA[j].x, s0); s0 = fmaf(qv.y, kA[j].y, s0);
                    s0 = fmaf(qv.z, kA[j].z, s0); s0 = fmaf(qv.w, kA[j].w, s0);
                    s1 = fmaf(qv.x, kB[j].x, s1); s1 = fmaf(qv.y, kB[j].y, s1);
                    s1 = fmaf(qv.z, kB[j].z, s1); s1 = fmaf(qv.w, kB[j].w, s1);
                }
                s0v[i] += s0;
                s1v[i] += s1;
            }
        }
    }
#pragma unroll
    for (int i = 0; i < 7; i++) { s0v[i] *= scale; s1v[i] *= scale; }

    float mx[7];
#pragma unroll
    for (int i = 0; i < 7; i++) mx[i] = hi ? fmaxf(s0v[i], s1v[i]) : s0v[i];
#pragma unroll
    for (int o = 16; o > 0; o >>= 1) {
#pragma unroll
        for (int i = 0; i < 7; i++)
            mx[i] = fmaxf(mx[i], __shfl_xor_sync(0xffffffffu, mx[i], o));
    }
    float e0a[7], e1a[7], sm[7];
#pragma unroll
    for (int i = 0; i < 7; i++) {
        e0a[i] = __expf(s0v[i] - mx[i]);
        e1a[i] = hi ? __expf(s1v[i] - mx[i]) : 0.f;
        sm[i] = e0a[i] + e1a[i];
    }
#pragma unroll
    for (int o = 16; o > 0; o >>= 1) {
#pragma unroll
        for (int i = 0; i < 7; i++)
            sm[i] += __shfl_xor_sync(0xffffffffu, sm[i], o);
    }
    float rinv[7];
#pragma unroll
    for (int i = 0; i < 7; i++) {
        rinv[i] = 1.f / sm[i];
        int p = warp + 8 * i;
        if (p < 49) {
            sP[p * 52 + lane] = e0a[i];
            if (lane < 17) sP[p * 52 + 32 + lane] = e1a[i];
        }
    }
    __syncthreads();

    float accv[7];
#pragma unroll
    for (int i = 0; i < 7; i++) accv[i] = 0.f;
#pragma unroll
    for (int j = 0; j < 13; j++) {
        float4 pv[7];
#pragma unroll
        for (int i = 0; i < 7; i++) {
            int p = warp + 8 * i;
            pv[i] = (p < 49) ? *(const float4*)&sP[p * 52 + 4 * j]
                             : make_float4(0.f, 0.f, 0.f, 0.f);
        }
        {
            float v0 = sV[(4 * j + 0) * 36 + lane];
#pragma unroll
            for (int i = 0; i < 7; i++) accv[i] = fmaf(pv[i].x, v0, accv[i]);
            float v1 = sV[(4 * j + 1) * 36 + lane];
#pragma unroll
            for (int i = 0; i < 7; i++) accv[i] = fmaf(pv[i].y, v1, accv[i]);
            float v2 = sV[(4 * j + 2) * 36 + lane];
#pragma unroll
            for (int i = 0; i < 7; i++) accv[i] = fmaf(pv[i].z, v2, accv[i]);
            float v3 = sV[(4 * j + 3) * 36 + lane];
#pragma unroll
            for (int i = 0; i < 7; i++) accv[i] = fmaf(pv[i].w, v3, accv[i]);
        }
    }

#pragma unroll
    for (int i = 0; i < 7; i++) {
        int p = warp + 8 * i;
        if (p < 49) {
            float val = accv[i] * rinv[i];
            __nv_bfloat16 h = __float2bfloat16(val);
            __nv_bfloat16 l = __float2bfloat16(val - __bfloat162float(h));
            int col = (headOff + hl) * 32 + lane;
            for (int t = 0; t < ntile; t++) {
                int nout = (t * nwin + rg) * 49 + p;
                size_t off = ((size_t)b * NTOK + nout) * 384 + col;
                g_Zh[off] = h;
                g_Zl[off] = l;
            }
        }
    }
}

// single launch, heavy (conv-bearing) CTAs scheduled first
__global__ __launch_bounds__(256, 3)
void attn_all(const float* __restrict__ c1w, const float* __restrict__ c1b,
              const float* __restrict__ c2w, const float* __restrict__ c2b)
{
    int bid = blockIdx.x;
    if (bid < 512)        attn_body(2, bid, c1w, c1b, c2w, c2b);
    else if (bid < 2560)  attn_body(1, bid - 512, c1w, c1b, c2w, c2b);
    else                  attn_body(0, bid - 2560, c1w, c1b, c2w, c2b);
}

// ---------------- launch ---------------------------------------------------------
extern "C" void kernel_launch(void* const* d_in, const int* in_sizes, int n_in,
                              void* d_out, int out_size)
{
    const float* x     = (const float*)d_in[0];
    const float* Wq    = (const float*)d_in[1];
    const float* Wkv   = (const float*)d_in[2];
    const float* Wproj = (const float*)d_in[3];
    const float* bproj = (const float*)d_in[4];
    const float* c1w   = (const float*)d_in[5];
    const float* c1b   = (const float*)d_in[6];
    const float* c2w   = (const float*)d_in[7];
    const float* c2b   = (const float*)d_in[8];
    float* out = (float*)d_out;

    cudaFuncSetAttribute(gemm_mma, cudaFuncAttributeMaxDynamicSharedMemorySize, SMEM_GEMM);

    split_fused<<<4704 + 2304, 256>>>((const float4*)x, Wq, Wkv, Wproj);
    gemm_mma<<<dim3(9, 784), 256, SMEM_GEMM>>>(nullptr, nullptr, 0);
    attn_all<<<10752, 256>>>(c1w, c1b, c2w, c2b);
    gemm_mma<<<dim3(3, 784), 256, SMEM_GEMM>>>(bproj, out, 1);
}